// round 3
// baseline (speedup 1.0000x reference)
#include <cuda_runtime.h>

#define N_NODES 20000
#define DIM     512
#define BATCH   2048
#define H1      128
#define H2      64
#define DRUG    2000
#define NSLOT   65              // 1 pos + 32 neg1 + 32 neg2 per batch element
#define NSAMP   (BATCH * NSLOT) // 133120
#define NGROUPS (NSAMP / 4)     // 33280

// Scratch tables (device globals; no allocation allowed in kernel_launch).
__device__ float g_Ptop[DRUG * H1];   // embed[0:2000] @ W1_top + b1
__device__ float g_Pbot[DRUG * H1];   // embed[0:2000] @ W1_bot
__device__ float g_Ptb [BATCH * H1];  // embed[t[b]]   @ W1_bot

// ---------------------------------------------------------------------------
// Stage 1: precompute layer-1 partial products.
// grid.y selects job: 0 = Ptop (rows 0..1999, W1[:512], +b1)
//                     1 = Pbot (rows 0..1999, W1[512:])
//                     2 = Ptb  (rows = t[b],  W1[512:])
// Each block: 16 rows x 128 cols, 256 threads, thread tile = 4 rows x 2 cols.
// ---------------------------------------------------------------------------
__global__ __launch_bounds__(256) void precompute_kernel(
    const float* __restrict__ embed,
    const float* __restrict__ W1,   // (1024, 128) row-major
    const float* __restrict__ b1,   // (128,)
    const int*   __restrict__ t)    // (B, 1)
{
    const int job   = blockIdx.y;
    const int nrows = (job == 2) ? BATCH : DRUG;
    const int row0  = blockIdx.x * 16;
    if (row0 >= nrows) return;

    const float* W = W1 + ((job == 0) ? 0 : DIM * H1);
    float* out = (job == 0) ? g_Ptop : ((job == 1) ? g_Pbot : g_Ptb);

    __shared__ float sA[16][DIM];   // 32 KB of embedding rows

    const int tid = threadIdx.x;

    // Cooperative load of 16 embedding rows (float4, coalesced).
    for (int idx = tid; idx < 16 * (DIM / 4); idx += 256) {
        int r  = idx / (DIM / 4);
        int k4 = idx % (DIM / 4);
        int row = row0 + r;
        int src = 0;
        if (row < nrows) src = (job == 2) ? t[row] : row;
        float4 v = reinterpret_cast<const float4*>(embed + (size_t)src * DIM)[k4];
        reinterpret_cast<float4*>(&sA[r][0])[k4] = v;
    }
    __syncthreads();

    const int cg = tid & 63;    // column pair 0..63
    const int rg = tid >> 6;    // row group   0..3
    const int c  = cg * 2;
    const int r0 = rg * 4;

    float acc[4][2] = {};
    #pragma unroll 8
    for (int k = 0; k < DIM; k++) {
        float2 w = *reinterpret_cast<const float2*>(W + k * H1 + c);
        #pragma unroll
        for (int r = 0; r < 4; r++) {
            float a = sA[r0 + r][k];   // warp-uniform -> LDS broadcast
            acc[r][0] += a * w.x;
            acc[r][1] += a * w.y;
        }
    }

    const float add0 = (job == 0) ? b1[c]     : 0.f;
    const float add1 = (job == 0) ? b1[c + 1] : 0.f;
    #pragma unroll
    for (int r = 0; r < 4; r++) {
        int row = row0 + r0 + r;
        if (row < nrows) {
            out[row * H1 + c]     = acc[r][0] + add0;
            out[row * H1 + c + 1] = acc[r][1] + add1;
        }
    }
}

// ---------------------------------------------------------------------------
// Stage 2: per-sample layers 1(add+relu) / 2 / 3.
// One warp processes 4 samples at a time (same slot, consecutive b).
// W2 lives in smem row-major; each lane owns output columns {2*lane, 2*lane+1}
// so the per-j LDS.64 is conflict-free and feeds 8 FMAs (4 samples x 2 cols).
// h1 values are broadcast across the warp with shfl.
// ---------------------------------------------------------------------------
__global__ __launch_bounds__(256) void mlp_tail_kernel(
    const float* __restrict__ W2,   // (128, 64) row-major
    const float* __restrict__ b2,   // (64,)
    const float* __restrict__ W3,   // (64, 1)
    const float* __restrict__ b3,   // (1,)
    const int*   __restrict__ h,    // (B, 1)
    const int*   __restrict__ n_s,  // (B, 64)
    float*       __restrict__ out)  // pos[B] then neg[B*64]
{
    __shared__ float sW2[H1 * H2];  // 32 KB
    __shared__ float sb2[H2];
    __shared__ float sW3[H2];
    __shared__ float sb3;

    const int tid = threadIdx.x;
    for (int i = tid; i < H1 * H2 / 4; i += 256)
        reinterpret_cast<float4*>(sW2)[i] = reinterpret_cast<const float4*>(W2)[i];
    if (tid < H2) { sb2[tid] = b2[tid]; sW3[tid] = W3[tid]; }
    if (tid == 0) sb3 = b3[0];
    __syncthreads();

    const int lane  = tid & 31;
    const int warp  = tid >> 5;
    const int gwarp = blockIdx.x * 8 + warp;
    const int nwarp = gridDim.x * 8;

    for (int grp = gwarp; grp < NGROUPS; grp += nwarp) {
        const int s0   = grp * 4;
        const int slot = s0 >> 11;      // sample id = slot*2048 + b
        const int b0   = s0 & (BATCH - 1);

        const float* top[4];
        const float* bot[4];
        int oidx[4];

        if (slot == 0) {                          // pos
            #pragma unroll
            for (int s = 0; s < 4; s++) {
                int b = b0 + s;
                top[s] = g_Ptop + h[b] * H1;
                bot[s] = g_Ptb  + b * H1;
                oidx[s] = b;
            }
        } else if (slot <= 32) {                  // neg1: k = slot-1
            int k = slot - 1;
            #pragma unroll
            for (int s = 0; s < 4; s++) {
                int b = b0 + s;
                top[s] = g_Ptop + h[b] * H1;
                bot[s] = g_Pbot + n_s[b * 64 + k] * H1;
                oidx[s] = BATCH + b * 64 + k;
            }
        } else {                                  // neg2: k = slot-33
            int k = slot - 33;
            #pragma unroll
            for (int s = 0; s < 4; s++) {
                int b = b0 + s;
                top[s] = g_Ptop + n_s[b * 64 + 32 + k] * H1;
                bot[s] = g_Ptb  + b * H1;
                oidx[s] = BATCH + b * 64 + 32 + k;
            }
        }

        // Layer 1: h1 = relu(top + bot); lane holds j = i*32 + lane, i<4.
        float h1r[4][4];
        #pragma unroll
        for (int s = 0; s < 4; s++)
            #pragma unroll
            for (int i = 0; i < 4; i++) {
                int j = i * 32 + lane;
                float v = top[s][j] + bot[s][j];
                h1r[s][i] = v > 0.f ? v : 0.f;
            }

        // Layer 2: acc[s] over columns {2*lane, 2*lane+1}.
        float2 acc[4] = {{0.f,0.f},{0.f,0.f},{0.f,0.f},{0.f,0.f}};
        for (int i = 0; i < 4; i++) {
            #pragma unroll
            for (int src = 0; src < 32; src++) {
                int j = i * 32 + src;
                float2 w = *reinterpret_cast<const float2*>(sW2 + j * H2 + lane * 2);
                #pragma unroll
                for (int s = 0; s < 4; s++) {
                    float v = __shfl_sync(0xffffffffu, h1r[s][i], src);
                    acc[s].x += v * w.x;
                    acc[s].y += v * w.y;
                }
            }
        }

        // Layer 3 + warp reduction.
        const float bb0 = sb2[lane * 2],     bb1 = sb2[lane * 2 + 1];
        const float w30 = sW3[lane * 2],     w31 = sW3[lane * 2 + 1];
        #pragma unroll
        for (int s = 0; s < 4; s++) {
            float v0 = acc[s].x + bb0; v0 = v0 > 0.f ? v0 : 0.f;
            float v1 = acc[s].y + bb1; v1 = v1 > 0.f ? v1 : 0.f;
            float r = v0 * w30 + v1 * w31;
            #pragma unroll
            for (int off = 16; off > 0; off >>= 1)
                r += __shfl_xor_sync(0xffffffffu, r, off);
            if (lane == 0) out[oidx[s]] = r + sb3;
        }
    }
}

// ---------------------------------------------------------------------------
// Input order (setup_inputs): embed, W1, b1, W2, b2, W3, b3, h, t, n_s
// Output: pos (B) followed by neg (B*64), both fp32.
// ---------------------------------------------------------------------------
extern "C" void kernel_launch(void* const* d_in, const int* in_sizes, int n_in,
                              void* d_out, int out_size)
{
    const float* embed = (const float*)d_in[0];
    const float* W1    = (const float*)d_in[1];
    const float* b1    = (const float*)d_in[2];
    const float* W2    = (const float*)d_in[3];
    const float* b2    = (const float*)d_in[4];
    const float* W3    = (const float*)d_in[5];
    const float* b3    = (const float*)d_in[6];
    const int*   h     = (const int*)d_in[7];
    const int*   t     = (const int*)d_in[8];
    const int*   n_s   = (const int*)d_in[9];
    float* out = (float*)d_out;

    // Stage 1: 3 jobs, 16 rows/block. max rows = 2048 -> 128 blocks in x.
    dim3 g1(128, 3);
    precompute_kernel<<<g1, 256>>>(embed, W1, b1, t);

    // Stage 2: grid-stride over 33280 groups of 4 samples.
    mlp_tail_kernel<<<888, 256>>>(W2, b2, W3, b3, h, n_s, out);
}

// round 4
// speedup vs baseline: 1.4195x; 1.4195x over previous
#include <cuda_runtime.h>

#define N_NODES 20000
#define DIM     512
#define BATCH   2048
#define H1      128
#define H2      64
#define DRUG    2000
#define NSAMP   (BATCH * 65)    // 133120
#define SPG     8               // samples per warp-group
#define NG8     (NSAMP / SPG)   // 16640

// Scratch tables (device globals; no allocation allowed).
__device__ float g_Ptop[DRUG * H1];   // embed[0:2000] @ W1_top + b1
__device__ float g_Pbot[DRUG * H1];   // embed[0:2000] @ W1_bot
__device__ float g_Ptb [BATCH * H1];  // embed[t[b]]   @ W1_bot

// ---------------------------------------------------------------------------
// Stage 1: layer-1 partial products.
// grid.y: 0 = Ptop (rows<2000, W1[:512], +b1), 1 = Pbot, 2 = Ptb (rows=t[b]).
// Block: 16 rows x 128 cols, 256 threads, thread tile 4 rows x 2 cols.
// k-loop unrolled x4 with float4 broadcast reads of sA.
// ---------------------------------------------------------------------------
__global__ __launch_bounds__(256) void precompute_kernel(
    const float* __restrict__ embed,
    const float* __restrict__ W1,   // (1024, 128) row-major
    const float* __restrict__ b1,   // (128,)
    const int*   __restrict__ t)    // (B, 1)
{
    const int job   = blockIdx.y;
    const int nrows = (job == 2) ? BATCH : DRUG;
    const int row0  = blockIdx.x * 16;
    if (row0 >= nrows) return;

    const float* W = W1 + ((job == 0) ? 0 : DIM * H1);
    float* out = (job == 0) ? g_Ptop : ((job == 1) ? g_Pbot : g_Ptb);

    __shared__ float sA[16][DIM];   // 32 KB

    const int tid = threadIdx.x;
    for (int idx = tid; idx < 16 * (DIM / 4); idx += 256) {
        int r  = idx / (DIM / 4);
        int k4 = idx % (DIM / 4);
        int row = row0 + r;
        int src = 0;
        if (row < nrows) src = (job == 2) ? t[row] : row;
        float4 v = reinterpret_cast<const float4*>(embed + (size_t)src * DIM)[k4];
        reinterpret_cast<float4*>(&sA[r][0])[k4] = v;
    }
    __syncthreads();

    const int cg = tid & 63;    // column pair 0..63 (== lane within warp-pair layout)
    const int rg = tid >> 6;    // row group   0..3  (uniform within a warp)
    const int c  = cg * 2;
    const int r0 = rg * 4;

    float acc[4][2] = {};
    #pragma unroll 2
    for (int k = 0; k < DIM; k += 4) {
        float2 w0 = *reinterpret_cast<const float2*>(W + (k + 0) * H1 + c);
        float2 w1 = *reinterpret_cast<const float2*>(W + (k + 1) * H1 + c);
        float2 w2 = *reinterpret_cast<const float2*>(W + (k + 2) * H1 + c);
        float2 w3 = *reinterpret_cast<const float2*>(W + (k + 3) * H1 + c);
        #pragma unroll
        for (int r = 0; r < 4; r++) {
            float4 a = *reinterpret_cast<const float4*>(&sA[r0 + r][k]);  // broadcast
            acc[r][0] += a.x * w0.x; acc[r][1] += a.x * w0.y;
            acc[r][0] += a.y * w1.x; acc[r][1] += a.y * w1.y;
            acc[r][0] += a.z * w2.x; acc[r][1] += a.z * w2.y;
            acc[r][0] += a.w * w3.x; acc[r][1] += a.w * w3.y;
        }
    }

    const float add0 = (job == 0) ? b1[c]     : 0.f;
    const float add1 = (job == 0) ? b1[c + 1] : 0.f;
    #pragma unroll
    for (int r = 0; r < 4; r++) {
        int row = row0 + r0 + r;
        if (row < nrows) {
            out[row * H1 + c]     = acc[r][0] + add0;
            out[row * H1 + c + 1] = acc[r][1] + add1;
        }
    }
}

// ---------------------------------------------------------------------------
// Stage 2: per-sample layers 1(add+relu) / 2 / 3.
// One warp processes SPG=8 samples. h1 is staged in per-warp smem and read
// back with broadcast LDS.128 (no shuffles in the hot loop). W2 in smem
// row-major; lane owns output cols {2*lane, 2*lane+1} -> conflict-free LDS.64.
// Dynamic smem layout: [0,8192) W2, [8192,16384) per-warp h1 staging.
// ---------------------------------------------------------------------------
__global__ __launch_bounds__(256) void mlp_tail_kernel(
    const float* __restrict__ W2,   // (128, 64) row-major
    const float* __restrict__ b2,   // (64,)
    const float* __restrict__ W3,   // (64, 1)
    const float* __restrict__ b3,   // (1,)
    const int*   __restrict__ h,    // (B, 1)
    const int*   __restrict__ n_s,  // (B, 64)
    float*       __restrict__ out)  // pos[B] then neg[B*64]
{
    extern __shared__ float dyn[];
    float* sW2 = dyn;                       // H1*H2 = 8192 floats
    float* sH1all = dyn + H1 * H2;          // 8 warps * SPG * H1 = 8192 floats

    __shared__ float sb2[H2];
    __shared__ float sW3[H2];
    __shared__ float sb3;

    const int tid = threadIdx.x;
    for (int i = tid; i < H1 * H2 / 4; i += 256)
        reinterpret_cast<float4*>(sW2)[i] = reinterpret_cast<const float4*>(W2)[i];
    if (tid < H2) { sb2[tid] = b2[tid]; sW3[tid] = W3[tid]; }
    if (tid == 0) sb3 = b3[0];
    __syncthreads();

    const int lane  = tid & 31;
    const int warp  = tid >> 5;
    float* sH1 = sH1all + warp * (SPG * H1);   // this warp's staging area

    const int gwarp = blockIdx.x * 8 + warp;
    const int nwarp = gridDim.x * 8;

    const float bb0 = sb2[lane * 2],  bb1 = sb2[lane * 2 + 1];
    const float w30 = sW3[lane * 2],  w31 = sW3[lane * 2 + 1];
    const float* wcol = sW2 + lane * 2;

    for (int grp = gwarp; grp < NG8; grp += nwarp) {
        const int s0   = grp * SPG;
        const int slot = s0 >> 11;           // 2048 % 8 == 0: group never straddles slots
        const int b0   = s0 & (BATCH - 1);

        int top_off[SPG], bot_off[SPG], oidx[SPG];
        const float* bot_tab;

        if (slot == 0) {                          // pos
            bot_tab = g_Ptb;
            #pragma unroll
            for (int s = 0; s < SPG; s++) {
                int b = b0 + s;
                top_off[s] = h[b] * H1;
                bot_off[s] = b * H1;
                oidx[s] = b;
            }
        } else if (slot <= 32) {                  // neg1: k = slot-1
            int k = slot - 1;
            bot_tab = g_Pbot;
            #pragma unroll
            for (int s = 0; s < SPG; s++) {
                int b = b0 + s;
                top_off[s] = h[b] * H1;
                bot_off[s] = n_s[b * 64 + k] * H1;
                oidx[s] = BATCH + b * 64 + k;
            }
        } else {                                  // neg2: k = slot-33
            int k = slot - 33;
            bot_tab = g_Ptb;
            #pragma unroll
            for (int s = 0; s < SPG; s++) {
                int b = b0 + s;
                top_off[s] = n_s[b * 64 + 32 + k] * H1;
                bot_off[s] = b * H1;
                oidx[s] = BATCH + b * 64 + 32 + k;
            }
        }

        // Layer 1: lane owns j = 4*lane..4*lane+3; stage relu(top+bot) to smem.
        __syncwarp();   // previous iteration's readers are done before we overwrite
        #pragma unroll
        for (int s = 0; s < SPG; s++) {
            float4 tv = *reinterpret_cast<const float4*>(g_Ptop + top_off[s] + 4 * lane);
            float4 bv = *reinterpret_cast<const float4*>(bot_tab + bot_off[s] + 4 * lane);
            float4 hv;
            hv.x = fmaxf(tv.x + bv.x, 0.f);
            hv.y = fmaxf(tv.y + bv.y, 0.f);
            hv.z = fmaxf(tv.z + bv.z, 0.f);
            hv.w = fmaxf(tv.w + bv.w, 0.f);
            *reinterpret_cast<float4*>(sH1 + s * H1 + 4 * lane) = hv;
        }
        __syncwarp();

        // Layer 2: acc[s] over cols {2*lane, 2*lane+1}; h1 via broadcast LDS.128.
        float2 acc[SPG];
        #pragma unroll
        for (int s = 0; s < SPG; s++) { acc[s].x = 0.f; acc[s].y = 0.f; }

        #pragma unroll 2
        for (int j = 0; j < H1; j += 4) {
            float2 w0 = *reinterpret_cast<const float2*>(wcol + (j + 0) * H2);
            float2 w1 = *reinterpret_cast<const float2*>(wcol + (j + 1) * H2);
            float2 w2 = *reinterpret_cast<const float2*>(wcol + (j + 2) * H2);
            float2 w3 = *reinterpret_cast<const float2*>(wcol + (j + 3) * H2);
            #pragma unroll
            for (int s = 0; s < SPG; s++) {
                float4 v = *reinterpret_cast<const float4*>(sH1 + s * H1 + j); // broadcast
                acc[s].x += v.x * w0.x; acc[s].y += v.x * w0.y;
                acc[s].x += v.y * w1.x; acc[s].y += v.y * w1.y;
                acc[s].x += v.z * w2.x; acc[s].y += v.z * w2.y;
                acc[s].x += v.w * w3.x; acc[s].y += v.w * w3.y;
            }
        }

        // Layer 3 + warp reduction.
        #pragma unroll
        for (int s = 0; s < SPG; s++) {
            float v0 = acc[s].x + bb0; v0 = v0 > 0.f ? v0 : 0.f;
            float v1 = acc[s].y + bb1; v1 = v1 > 0.f ? v1 : 0.f;
            float r = v0 * w30 + v1 * w31;
            #pragma unroll
            for (int off = 16; off > 0; off >>= 1)
                r += __shfl_xor_sync(0xffffffffu, r, off);
            if (lane == 0) out[oidx[s]] = r + sb3;
        }
    }
}

// ---------------------------------------------------------------------------
// Input order: embed, W1, b1, W2, b2, W3, b3, h, t, n_s
// Output: pos (B) followed by neg (B*64), fp32.
// ---------------------------------------------------------------------------
extern "C" void kernel_launch(void* const* d_in, const int* in_sizes, int n_in,
                              void* d_out, int out_size)
{
    const float* embed = (const float*)d_in[0];
    const float* W1    = (const float*)d_in[1];
    const float* b1    = (const float*)d_in[2];
    const float* W2    = (const float*)d_in[3];
    const float* b2    = (const float*)d_in[4];
    const float* W3    = (const float*)d_in[5];
    const float* b3    = (const float*)d_in[6];
    const int*   h     = (const int*)d_in[7];
    const int*   t     = (const int*)d_in[8];
    const int*   n_s   = (const int*)d_in[9];
    float* out = (float*)d_out;

    // Stage 1: 3 jobs, 16 rows/block (max rows 2048 -> 128 blocks in x).
    dim3 g1(128, 3);
    precompute_kernel<<<g1, 256>>>(embed, W1, b1, t);

    // Stage 2: 416 blocks x 8 warps = 3328 warps; 16640 groups -> exactly 5 per warp.
    const int smem_bytes = (H1 * H2 + 8 * SPG * H1) * sizeof(float);  // 64 KB
    cudaFuncSetAttribute(mlp_tail_kernel,
                         cudaFuncAttributeMaxDynamicSharedMemorySize, smem_bytes);
    mlp_tail_kernel<<<416, 256, smem_bytes>>>(W2, b2, W3, b3, h, n_s, out);
}

// round 5
// speedup vs baseline: 2.0697x; 1.4581x over previous
#include <cuda_runtime.h>

#define N_NODES 20000
#define DIM     512
#define BATCH   2048
#define H1      128
#define H2      64
#define DRUG    2000
#define NSAMP   (BATCH * 65)    // 133120
#define SPG     8               // samples per warp-group (4 packed pairs)
#define NG8     (NSAMP / SPG)   // 16640

typedef unsigned long long u64;

// Scratch tables (device globals; no allocation allowed).
__device__ float g_Ptop[DRUG * H1];   // embed[0:2000] @ W1_top + b1
__device__ float g_Pbot[DRUG * H1];   // embed[0:2000] @ W1_bot
__device__ float g_Ptb [BATCH * H1];  // embed[t[b]]   @ W1_bot

// ---- packed fp32x2 helpers (sm_100+): FFMA2, 2 MACs per issue slot ----
__device__ __forceinline__ u64 pack2(float lo, float hi) {
    u64 r; asm("mov.b64 %0, {%1, %2};" : "=l"(r) : "f"(lo), "f"(hi)); return r;
}
__device__ __forceinline__ void unpack2(float& lo, float& hi, u64 v) {
    asm("mov.b64 {%0, %1}, %2;" : "=f"(lo), "=f"(hi) : "l"(v));
}
__device__ __forceinline__ u64 fma2(u64 a, u64 b, u64 c) {
    u64 d; asm("fma.rn.f32x2 %0, %1, %2, %3;" : "=l"(d) : "l"(a), "l"(b), "l"(c));
    return d;
}

// ---------------------------------------------------------------------------
// Stage 1: layer-1 partial products (unchanged from R4).
// ---------------------------------------------------------------------------
__global__ __launch_bounds__(256) void precompute_kernel(
    const float* __restrict__ embed,
    const float* __restrict__ W1,   // (1024, 128) row-major
    const float* __restrict__ b1,   // (128,)
    const int*   __restrict__ t)    // (B, 1)
{
    const int job   = blockIdx.y;
    const int nrows = (job == 2) ? BATCH : DRUG;
    const int row0  = blockIdx.x * 16;
    if (row0 >= nrows) return;

    const float* W = W1 + ((job == 0) ? 0 : DIM * H1);
    float* out = (job == 0) ? g_Ptop : ((job == 1) ? g_Pbot : g_Ptb);

    __shared__ float sA[16][DIM];   // 32 KB

    const int tid = threadIdx.x;
    for (int idx = tid; idx < 16 * (DIM / 4); idx += 256) {
        int r  = idx / (DIM / 4);
        int k4 = idx % (DIM / 4);
        int row = row0 + r;
        int src = 0;
        if (row < nrows) src = (job == 2) ? t[row] : row;
        float4 v = reinterpret_cast<const float4*>(embed + (size_t)src * DIM)[k4];
        reinterpret_cast<float4*>(&sA[r][0])[k4] = v;
    }
    __syncthreads();

    const int cg = tid & 63;
    const int rg = tid >> 6;
    const int c  = cg * 2;
    const int r0 = rg * 4;

    float acc[4][2] = {};
    #pragma unroll 2
    for (int k = 0; k < DIM; k += 4) {
        float2 w0 = *reinterpret_cast<const float2*>(W + (k + 0) * H1 + c);
        float2 w1 = *reinterpret_cast<const float2*>(W + (k + 1) * H1 + c);
        float2 w2 = *reinterpret_cast<const float2*>(W + (k + 2) * H1 + c);
        float2 w3 = *reinterpret_cast<const float2*>(W + (k + 3) * H1 + c);
        #pragma unroll
        for (int r = 0; r < 4; r++) {
            float4 a = *reinterpret_cast<const float4*>(&sA[r0 + r][k]);  // broadcast
            acc[r][0] += a.x * w0.x; acc[r][1] += a.x * w0.y;
            acc[r][0] += a.y * w1.x; acc[r][1] += a.y * w1.y;
            acc[r][0] += a.z * w2.x; acc[r][1] += a.z * w2.y;
            acc[r][0] += a.w * w3.x; acc[r][1] += a.w * w3.y;
        }
    }

    const float add0 = (job == 0) ? b1[c]     : 0.f;
    const float add1 = (job == 0) ? b1[c + 1] : 0.f;
    #pragma unroll
    for (int r = 0; r < 4; r++) {
        int row = row0 + r0 + r;
        if (row < nrows) {
            out[row * H1 + c]     = acc[r][0] + add0;
            out[row * H1 + c + 1] = acc[r][1] + add1;
        }
    }
}

// ---------------------------------------------------------------------------
// Stage 2: one warp = 8 samples = 4 packed sample-pairs.
// Layer-1 output staged in per-warp smem INTERLEAVED by pair so the layer-2
// operand (h1[2p][j], h1[2p+1][j]) is read pre-packed via broadcast LDS.128.
// 16B blocks XOR-swizzled ((jq&7)^m) so the staging stores are conflict-free.
// Layer-2 inner loop: fma.rn.f32x2 -> FFMA2, 2 MACs/slot.
// Dynamic smem: [0,8192) W2 floats, [8192,16384) 8 warps x 1024-float staging.
// ---------------------------------------------------------------------------
__global__ __launch_bounds__(256) void mlp_tail_kernel(
    const float* __restrict__ W2,   // (128, 64) row-major
    const float* __restrict__ b2,   // (64,)
    const float* __restrict__ W3,   // (64, 1)
    const float* __restrict__ b3,   // (1,)
    const int*   __restrict__ h,    // (B, 1)
    const int*   __restrict__ n_s,  // (B, 64)
    float*       __restrict__ out)  // pos[B] then neg[B*64]
{
    extern __shared__ float dyn[];
    float* sW2 = dyn;                       // H1*H2 = 8192 floats
    float* sH1all = dyn + H1 * H2;          // 8 warps * 1024 floats

    __shared__ float sb2[H2];
    __shared__ float sW3[H2];
    __shared__ float sb3;

    const int tid = threadIdx.x;
    for (int i = tid; i < H1 * H2 / 4; i += 256)
        reinterpret_cast<float4*>(sW2)[i] = reinterpret_cast<const float4*>(W2)[i];
    if (tid < H2) { sb2[tid] = b2[tid]; sW3[tid] = W3[tid]; }
    if (tid == 0) sb3 = b3[0];
    __syncthreads();

    const int lane = tid & 31;
    const int warp = tid >> 5;
    char* sH1b = reinterpret_cast<char*>(sH1all + warp * 1024);  // 4 KB staging

    const int gwarp = blockIdx.x * 8 + warp;
    const int nwarp = gridDim.x * 8;

    const float bb0 = sb2[lane * 2],  bb1 = sb2[lane * 2 + 1];
    const float w30 = sW3[lane * 2],  w31 = sW3[lane * 2 + 1];
    const float* wcol = sW2 + lane * 2;

    // Staging ownership: lane stages pair p_own, j-range [j0, j0+16).
    const int p_own = lane >> 3;
    const int m     = lane & 7;
    const int j0    = m * 16;

    for (int grp = gwarp; grp < NG8; grp += nwarp) {
        const int s0   = grp * SPG;
        const int slot = s0 >> 11;           // 2048 % 8 == 0: no slot straddle
        const int b0   = s0 & (BATCH - 1);

        int top_off[SPG], bot_off[SPG], oidx[SPG];
        const float* bot_tab;

        if (slot == 0) {                          // pos
            bot_tab = g_Ptb;
            #pragma unroll
            for (int s = 0; s < SPG; s++) {
                int b = b0 + s;
                top_off[s] = h[b] * H1;
                bot_off[s] = b * H1;
                oidx[s] = b;
            }
        } else if (slot <= 32) {                  // neg1: k = slot-1
            int k = slot - 1;
            bot_tab = g_Pbot;
            #pragma unroll
            for (int s = 0; s < SPG; s++) {
                int b = b0 + s;
                top_off[s] = h[b] * H1;
                bot_off[s] = n_s[b * 64 + k] * H1;
                oidx[s] = BATCH + b * 64 + k;
            }
        } else {                                  // neg2: k = slot-33
            int k = slot - 33;
            bot_tab = g_Ptb;
            #pragma unroll
            for (int s = 0; s < SPG; s++) {
                int b = b0 + s;
                top_off[s] = n_s[b * 64 + 32 + k] * H1;
                bot_off[s] = b * H1;
                oidx[s] = BATCH + b * 64 + 32 + k;
            }
        }

        // ---- Layer 1: compute relu(top+bot) for pair p_own, stage interleaved.
        __syncwarp();   // prior iteration's readers done before overwrite
        {
            const float* ta = g_Ptop  + top_off[2 * p_own]     + j0;
            const float* tb = g_Ptop  + top_off[2 * p_own + 1] + j0;
            const float* ba = bot_tab + bot_off[2 * p_own]     + j0;
            const float* bb = bot_tab + bot_off[2 * p_own + 1] + j0;
            char* base = sH1b + p_own * 1024 + m * 128;
            #pragma unroll
            for (int q = 0; q < 4; q++) {
                float4 a0 = *reinterpret_cast<const float4*>(ta + 4 * q);
                float4 a1 = *reinterpret_cast<const float4*>(ba + 4 * q);
                float4 c0 = *reinterpret_cast<const float4*>(tb + 4 * q);
                float4 c1 = *reinterpret_cast<const float4*>(bb + 4 * q);
                float4 ha, hb;
                ha.x = fmaxf(a0.x + a1.x, 0.f); ha.y = fmaxf(a0.y + a1.y, 0.f);
                ha.z = fmaxf(a0.z + a1.z, 0.f); ha.w = fmaxf(a0.w + a1.w, 0.f);
                hb.x = fmaxf(c0.x + c1.x, 0.f); hb.y = fmaxf(c0.y + c1.y, 0.f);
                hb.z = fmaxf(c0.z + c1.z, 0.f); hb.w = fmaxf(c0.w + c1.w, 0.f);
                float4 lo = make_float4(ha.x, hb.x, ha.y, hb.y);  // j=j0+4q,   +1
                float4 hi = make_float4(ha.z, hb.z, ha.w, hb.w);  // j=j0+4q+2, +3
                *reinterpret_cast<float4*>(base + (((2*q + 0) ^ m) << 4)) = lo;
                *reinterpret_cast<float4*>(base + (((2*q + 1) ^ m) << 4)) = hi;
            }
        }
        __syncwarp();

        // ---- Layer 2: packed-pair FFMA2 over cols {2*lane, 2*lane+1}.
        u64 acc[4][2];
        #pragma unroll
        for (int p = 0; p < 4; p++) { acc[p][0] = 0ull; acc[p][1] = 0ull; }

        #pragma unroll 4
        for (int j = 0; j < H1; j += 2) {
            float2 wA = *reinterpret_cast<const float2*>(wcol + (j + 0) * H2);
            float2 wB = *reinterpret_cast<const float2*>(wcol + (j + 1) * H2);
            u64 wA0 = pack2(wA.x, wA.x), wA1 = pack2(wA.y, wA.y);
            u64 wB0 = pack2(wB.x, wB.x), wB1 = pack2(wB.y, wB.y);
            const int jq  = j >> 1;
            const int mm  = jq >> 3;
            const int off = mm * 128 + (((jq & 7) ^ mm) << 4);
            #pragma unroll
            for (int p = 0; p < 4; p++) {
                ulonglong2 v = *reinterpret_cast<const ulonglong2*>(
                                   sH1b + p * 1024 + off);       // broadcast LDS.128
                acc[p][0] = fma2(v.x, wA0, acc[p][0]);
                acc[p][1] = fma2(v.x, wA1, acc[p][1]);
                acc[p][0] = fma2(v.y, wB0, acc[p][0]);
                acc[p][1] = fma2(v.y, wB1, acc[p][1]);
            }
        }

        // ---- Layer 3 + warp reduction (per sample).
        #pragma unroll
        for (int p = 0; p < 4; p++) {
            float c0lo, c0hi, c1lo, c1hi;
            unpack2(c0lo, c0hi, acc[p][0]);
            unpack2(c1lo, c1hi, acc[p][1]);
            {   // sample 2p
                float v0 = fmaxf(c0lo + bb0, 0.f);
                float v1 = fmaxf(c1lo + bb1, 0.f);
                float r = v0 * w30 + v1 * w31;
                #pragma unroll
                for (int off = 16; off > 0; off >>= 1)
                    r += __shfl_xor_sync(0xffffffffu, r, off);
                if (lane == 0) out[oidx[2 * p]] = r + sb3;
            }
            {   // sample 2p+1
                float v0 = fmaxf(c0hi + bb0, 0.f);
                float v1 = fmaxf(c1hi + bb1, 0.f);
                float r = v0 * w30 + v1 * w31;
                #pragma unroll
                for (int off = 16; off > 0; off >>= 1)
                    r += __shfl_xor_sync(0xffffffffu, r, off);
                if (lane == 0) out[oidx[2 * p + 1]] = r + sb3;
            }
        }
    }
}

// ---------------------------------------------------------------------------
// Input order: embed, W1, b1, W2, b2, W3, b3, h, t, n_s
// Output: pos (B) followed by neg (B*64), fp32.
// ---------------------------------------------------------------------------
extern "C" void kernel_launch(void* const* d_in, const int* in_sizes, int n_in,
                              void* d_out, int out_size)
{
    const float* embed = (const float*)d_in[0];
    const float* W1    = (const float*)d_in[1];
    const float* b1    = (const float*)d_in[2];
    const float* W2    = (const float*)d_in[3];
    const float* b2    = (const float*)d_in[4];
    const float* W3    = (const float*)d_in[5];
    const float* b3    = (const float*)d_in[6];
    const int*   h     = (const int*)d_in[7];
    const int*   t     = (const int*)d_in[8];
    const int*   n_s   = (const int*)d_in[9];
    float* out = (float*)d_out;

    dim3 g1(128, 3);
    precompute_kernel<<<g1, 256>>>(embed, W1, b1, t);

    const int smem_bytes = (H1 * H2 + 8 * SPG * H1) * sizeof(float);  // 64 KB
    cudaFuncSetAttribute(mlp_tail_kernel,
                         cudaFuncAttributeMaxDynamicSharedMemorySize, smem_bytes);
    mlp_tail_kernel<<<416, 256, smem_bytes>>>(W2, b2, W3, b3, h, n_s, out);
}